// round 6
// baseline (speedup 1.0000x reference)
#include <cuda_runtime.h>
#include <cuda_bf16.h>
#include <math.h>
#include <stdint.h>

// Problem constants
#define BATCH   8192
#define IN_DIM  64
#define HID     256
#define OUT_DIM 4096          // main distribution columns (h2 cols 1..4096)
#define K0PAD   80            // IN_DIM+1 padded to multiple of 16

// ---------------- static device scratch (no dynamic allocation allowed) ----------------
// __align__(256): these buffers are read with LDG.128 in the GEMM; wide ops on
// misaligned addresses trap (err715). Language only guarantees 4B alignment here.
__device__ __align__(256) float g_Xc [BATCH * K0PAD];
__device__ __align__(256) float g_W0p[HID * K0PAD];
__device__ __align__(256) float g_T0 [BATCH * HID];
__device__ __align__(256) float g_T1 [BATCH * HID];
__device__ __align__(256) float g_H2 [(size_t)BATCH * OUT_DIM];

// ---------------- prep: concat+pad X, pad W0, in one launch ----------------
__global__ void prep_kernel(const float* __restrict__ x,
                            const float* __restrict__ klb,
                            const float* __restrict__ W0,
                            float* __restrict__ Xc,
                            float* __restrict__ W0p) {
    int i = blockIdx.x * blockDim.x + threadIdx.x;
    if (i < BATCH * K0PAD) {
        int r = i / K0PAD, c = i % K0PAD;
        float v = 0.f;
        if (c < IN_DIM)       v = x[r * IN_DIM + c];
        else if (c == IN_DIM) v = klb[r];
        Xc[i] = v;
    }
    if (i < HID * K0PAD) {
        int r = i / K0PAD, c = i % K0PAD;
        W0p[i] = (c < IN_DIM + 1) ? W0[r * (IN_DIM + 1) + c] : 0.f;
    }
}

// ---------------- SGEMM: C[M,N] = actopt( A[M,K] @ W[N,K]^T + bias[N] ) ----------------
// 128x128 tile, BK=16, 256 threads, 8x8 per-thread micro-tile, double-buffered smem.
// K, N compile-time: all address arithmetic strength-reduces to immediates.
// Requires: M%128==0, N%128==0, K%16==0, A/W row starts 16B-aligned.
template<int K, int N, bool TANH>
__global__ __launch_bounds__(256)
void sgemm128_kernel(const float* __restrict__ A, const float* __restrict__ W,
                     const float* __restrict__ bias, float* __restrict__ C,
                     int M) {
    constexpr int BM = 128, BN = 128, BK = 16;
    constexpr int NK = K / BK;
    __shared__ float As[2][BK][BM];
    __shared__ float Bs[2][BK][BN];

    const int tid = threadIdx.x;
    const int m0 = blockIdx.y * BM;
    const int n0 = blockIdx.x * BN;

    // global->smem load mapping: 512 float4 per operand tile, 2 per thread
    const int lrow0 = tid >> 2;            // 0..63
    const int lk    = (tid & 3) * 4;       // 0,4,8,12
    const float* Ap = A + (size_t)m0 * K;
    const float* Wp = W + (size_t)n0 * K;

    // compute mapping
    const int tx = tid & 15;               // N direction
    const int ty = tid >> 4;               // M direction

    float acc[8][8];
    #pragma unroll
    for (int i = 0; i < 8; i++)
        #pragma unroll
        for (int j = 0; j < 8; j++) acc[i][j] = 0.f;

    // load tile 0
    {
        #pragma unroll
        for (int h = 0; h < 2; h++) {
            int row = lrow0 + h * 64;
            float4 va = *(const float4*)(Ap + (size_t)row * K + lk);
            As[0][lk + 0][row] = va.x; As[0][lk + 1][row] = va.y;
            As[0][lk + 2][row] = va.z; As[0][lk + 3][row] = va.w;
            float4 vb = *(const float4*)(Wp + (size_t)row * K + lk);
            Bs[0][lk + 0][row] = vb.x; Bs[0][lk + 1][row] = vb.y;
            Bs[0][lk + 2][row] = vb.z; Bs[0][lk + 3][row] = vb.w;
        }
    }
    __syncthreads();

    #pragma unroll 1
    for (int kt = 0; kt < NK; kt++) {
        const int s = kt & 1;
        float4 pa[2], pb[2];
        const bool more = (kt + 1 < NK);
        if (more) {
            int k0n = (kt + 1) * BK;
            #pragma unroll
            for (int h = 0; h < 2; h++) {
                int row = lrow0 + h * 64;
                pa[h] = *(const float4*)(Ap + (size_t)row * K + k0n + lk);
                pb[h] = *(const float4*)(Wp + (size_t)row * K + k0n + lk);
            }
        }

        #pragma unroll
        for (int k = 0; k < BK; k++) {
            float4 a0 = *(const float4*)&As[s][k][ty * 4];
            float4 a1 = *(const float4*)&As[s][k][64 + ty * 4];
            float4 b0 = *(const float4*)&Bs[s][k][tx * 4];
            float4 b1 = *(const float4*)&Bs[s][k][64 + tx * 4];
            float av[8] = {a0.x, a0.y, a0.z, a0.w, a1.x, a1.y, a1.z, a1.w};
            float bv[8] = {b0.x, b0.y, b0.z, b0.w, b1.x, b1.y, b1.z, b1.w};
            #pragma unroll
            for (int i = 0; i < 8; i++)
                #pragma unroll
                for (int j = 0; j < 8; j++)
                    acc[i][j] = fmaf(av[i], bv[j], acc[i][j]);
        }

        if (more) {
            const int d = s ^ 1;
            #pragma unroll
            for (int h = 0; h < 2; h++) {
                int row = lrow0 + h * 64;
                As[d][lk + 0][row] = pa[h].x; As[d][lk + 1][row] = pa[h].y;
                As[d][lk + 2][row] = pa[h].z; As[d][lk + 3][row] = pa[h].w;
                Bs[d][lk + 0][row] = pb[h].x; Bs[d][lk + 1][row] = pb[h].y;
                Bs[d][lk + 2][row] = pb[h].z; Bs[d][lk + 3][row] = pb[h].w;
            }
        }
        __syncthreads();
    }

    // epilogue
    #pragma unroll
    for (int i = 0; i < 8; i++) {
        int r = m0 + ((i < 4) ? (ty * 4 + i) : (64 + ty * 4 + i - 4));
        #pragma unroll
        for (int g = 0; g < 2; g++) {
            int c0 = n0 + g * 64 + tx * 4;
            float4 v;
            float* vp = &v.x;
            #pragma unroll
            for (int j = 0; j < 4; j++) {
                float val = acc[i][g * 4 + j] + bias[c0 + j];
                if (TANH) val = tanhf(val);
                vp[j] = val;
            }
            *(float4*)(C + (size_t)r * N + c0) = v;
        }
    }
}

// ---------------- block reductions (512 threads) ----------------
__device__ __forceinline__ float warp_sum(float v) {
    #pragma unroll
    for (int o = 16; o; o >>= 1) v += __shfl_xor_sync(0xffffffffu, v, o);
    return v;
}
__device__ __forceinline__ float warp_max(float v) {
    #pragma unroll
    for (int o = 16; o; o >>= 1) v = fmaxf(v, __shfl_xor_sync(0xffffffffu, v, o));
    return v;
}

// sm must have >= 40 floats
__device__ __forceinline__ float block_allreduce_sum(float v, float* sm) {
    int w = threadIdx.x >> 5, l = threadIdx.x & 31;
    v = warp_sum(v);
    if (l == 0) sm[w] = v;
    __syncthreads();
    if (w == 0) {
        float t = (l < 16) ? sm[l] : 0.f;
        t = warp_sum(t);
        if (l == 0) sm[32] = t;
    }
    __syncthreads();
    return sm[32];
}
__device__ __forceinline__ float block_allreduce_max(float v, float* sm) {
    int w = threadIdx.x >> 5, l = threadIdx.x & 31;
    v = warp_max(v);
    if (l == 0) sm[w] = v;
    __syncthreads();
    if (w == 0) {
        float t = (l < 16) ? sm[l] : -INFINITY;
        t = warp_max(t);
        if (l == 0) sm[32] = t;
    }
    __syncthreads();
    return sm[32];
}
__device__ __forceinline__ float2 block_allreduce_sum2(float a, float b, float* sm) {
    int w = threadIdx.x >> 5, l = threadIdx.x & 31;
    a = warp_sum(a); b = warp_sum(b);
    if (l == 0) { sm[w] = a; sm[16 + w] = b; }
    __syncthreads();
    if (w == 0) {
        float ta = (l < 16) ? sm[l] : 0.f;
        float tb = (l < 16) ? sm[16 + l] : 0.f;
        ta = warp_sum(ta); tb = warp_sum(tb);
        if (l == 0) { sm[32] = ta; sm[33] = tb; }
    }
    __syncthreads();
    return make_float2(sm[32], sm[33]);
}

// ---------------- fused head + normalize + KL-solver + output ----------------
// One CTA (512 threads) per batch row; 8 elements/thread, fully register-resident.
__global__ __launch_bounds__(512)
void solver_kernel(const float* __restrict__ T1, const float* __restrict__ W2,
                   const float* __restrict__ b2, const float* __restrict__ H2,
                   const float* __restrict__ logb, const float* __restrict__ klb,
                   const int* __restrict__ actions_left, float* __restrict__ out) {
    __shared__ float sm[40];
    const int row = blockIdx.x;
    const int tid = threadIdx.x;

    // --- kl head: h2[:,0] = dot(T1[row], W2[0]) + b2[0] ---
    float p = 0.f;
    for (int k = tid; k < HID; k += 512)
        p += T1[(size_t)row * HID + k] * W2[k];
    float kl_head = block_allreduce_sum(p, sm) + b2[0];
    float z = kl_head - __logf((float)(*actions_left));
    float kt = (1.f / (1.f + __expf(-z))) * klb[row] + 1e-6f;

    // --- load row, compute log-softmax normalizer of (h2 + logb) ---
    const size_t base = (size_t)row * OUT_DIM;
    float h2v[8], lb[8];
    float mx = -INFINITY;
    #pragma unroll
    for (int e = 0; e < 8; e++) {
        int j = tid + e * 512;
        h2v[e] = H2[base + j];
        lb[e]  = logb[base + j];
        mx = fmaxf(mx, h2v[e] + lb[e]);
    }
    mx = block_allreduce_max(mx, sm);
    float se = 0.f;
    #pragma unroll
    for (int e = 0; e < 8; e++) se += __expf(h2v[e] + lb[e] - mx);
    se = block_allreduce_sum(se, sm);
    const float S = mx + __logf(se);   // logsumexp(h2 + logb)

    // r = a/b = exp(h2 - S);  b = exp(logb)
    float rm1[8], bb[8];
    #pragma unroll
    for (int e = 0; e < 8; e++) {
        float r = __expf(h2v[e] - S);
        rm1[e] = r - 1.f;
        bb[e]  = __expf(lb[e]);
    }

    // --- 20 Newton/bisection steps ---
    // t = x/b = 1 + alpha*(r-1); clamp t away from 0 so log(t) stays finite
    // even if r underflowed (the underflowed element's true contribution is
    // ~0, and b*1e-30*log(1e-30) ~ 0, matching JAX's finite logspace math).
    float alpha = 1.f, bot = 0.f, top = 1.f;
    #pragma unroll 1
    for (int it = 0; it < 20; it++) {
        float klp = 0.f, dp = 0.f;
        #pragma unroll
        for (int e = 0; e < 8; e++) {
            float t = fmaxf(fmaf(alpha, rm1[e], 1.f), 1e-30f);  // x/b
            float L = __logf(t);                                // logx - logb
            klp = fmaf(bb[e] * t, L, klp);                      // sum x*(logx-logb)
            dp  = fmaf(bb[e] * rm1[e], L + 1.f, dp);            // sum (a-b)*(logx-logb+1)
        }
        float2 kd = block_allreduce_sum2(klp, dp, sm);
        float kl = kd.x, d = kd.y;
        bot = (kt >= kl) ? alpha : bot;                  // matches jnp.where semantics
        top = (kt <= kl) ? alpha : top;
        float delta = (kt - kl) / (d + 1e-12f);
        float lo = bot * 0.9375f + top * 0.0625f;
        float hi = 0.5f * (bot + top);
        alpha = fminf(fmaxf(alpha + delta, lo), hi);
    }

    // --- final evaluation at converged alpha; softmax(logx) = x / sum(x) ---
    float xs[8];
    float klp = 0.f, sp = 0.f;
    #pragma unroll
    for (int e = 0; e < 8; e++) {
        float t = fmaxf(fmaf(alpha, rm1[e], 1.f), 1e-30f);
        float L = __logf(t);
        float xv = bb[e] * t;
        xs[e] = xv;
        klp = fmaf(xv, L, klp);
        sp += xv;
    }
    float2 ks = block_allreduce_sum2(klp, sp, sm);
    float inv = 1.f / ks.y;
    #pragma unroll
    for (int e = 0; e < 8; e++)
        out[base + tid + e * 512] = xs[e] * inv;
    if (tid == 0) {
        float dk = ks.x - kt;
        out[(size_t)BATCH * OUT_DIM + row] = dk * dk;
    }
}

// ---------------- launch ----------------
extern "C" void kernel_launch(void* const* d_in, const int* in_sizes, int n_in,
                              void* d_out, int out_size) {
    const float* x    = (const float*)d_in[0];
    const float* klb  = (const float*)d_in[1];
    const float* logb = (const float*)d_in[2];
    const float* W0   = (const float*)d_in[3];
    const float* b0   = (const float*)d_in[4];
    const float* W1   = (const float*)d_in[5];
    const float* b1   = (const float*)d_in[6];
    const float* W2   = (const float*)d_in[7];
    const float* b2   = (const float*)d_in[8];
    const int*   al   = (const int*)  d_in[9];
    float* out = (float*)d_out;

    float *Xc, *W0p, *T0, *T1, *H2;
    cudaGetSymbolAddress((void**)&Xc,  g_Xc);
    cudaGetSymbolAddress((void**)&W0p, g_W0p);
    cudaGetSymbolAddress((void**)&T0,  g_T0);
    cudaGetSymbolAddress((void**)&T1,  g_T1);
    cudaGetSymbolAddress((void**)&H2,  g_H2);

    // prep (single launch covers both Xc and W0p ranges)
    prep_kernel<<<(BATCH * K0PAD + 255) / 256, 256>>>(x, klb, W0, Xc, W0p);

    // layer 0: T0 = tanh(Xc @ W0p^T + b0)   [8192,256], K=80
    {
        dim3 grid(HID / 128, BATCH / 128);
        sgemm128_kernel<K0PAD, HID, true><<<grid, 256>>>(Xc, W0p, b0, T0, BATCH);
    }
    // layer 1: T1 = tanh(T0 @ W1^T + b1)    [8192,256], K=256
    {
        dim3 grid(HID / 128, BATCH / 128);
        sgemm128_kernel<HID, HID, true><<<grid, 256>>>(T0, W1, b1, T1, BATCH);
    }
    // layer 2 (main cols 1..4096): H2 = T1 @ W2[1:]^T + b2[1:]   [8192,4096], K=256
    {
        dim3 grid(OUT_DIM / 128, BATCH / 128);
        sgemm128_kernel<HID, OUT_DIM, false><<<grid, 256>>>(T1, W2 + HID, b2 + 1, H2, BATCH);
    }
    // fused head + solver + output
    solver_kernel<<<BATCH, 512>>>(T1, W2, b2, H2, logb, klb, al, out);
}

// round 11
// speedup vs baseline: 1.0370x; 1.0370x over previous
#include <cuda_runtime.h>
#include <cuda_bf16.h>
#include <math.h>
#include <stdint.h>

// Problem constants
#define BATCH   8192
#define IN_DIM  64
#define HID     256
#define OUT_DIM 4096          // main distribution columns (h2 cols 1..4096)
#define K0PAD   80            // IN_DIM+1 padded to multiple of 16

// ---------------- static device scratch (no dynamic allocation allowed) ----------------
// __align__(256): these buffers are read with LDG.128 in the GEMM; wide ops on
// misaligned addresses trap (err715).
__device__ __align__(256) float g_Xc [BATCH * K0PAD];
__device__ __align__(256) float g_W0p[HID * K0PAD];
__device__ __align__(256) float g_T0 [BATCH * HID];
__device__ __align__(256) float g_T1 [BATCH * HID];
__device__ __align__(256) float g_H2 [(size_t)BATCH * OUT_DIM];

// ---------------- prep: concat+pad X, pad W0, in one launch ----------------
__global__ void prep_kernel(const float* __restrict__ x,
                            const float* __restrict__ klb,
                            const float* __restrict__ W0,
                            float* __restrict__ Xc,
                            float* __restrict__ W0p) {
    int i = blockIdx.x * blockDim.x + threadIdx.x;
    if (i < BATCH * K0PAD) {
        int r = i / K0PAD, c = i % K0PAD;
        float v = 0.f;
        if (c < IN_DIM)       v = x[r * IN_DIM + c];
        else if (c == IN_DIM) v = klb[r];
        Xc[i] = v;
    }
    if (i < HID * K0PAD) {
        int r = i / K0PAD, c = i % K0PAD;
        W0p[i] = (c < IN_DIM + 1) ? W0[r * (IN_DIM + 1) + c] : 0.f;
    }
}

// ---------------- SGEMM: C[M,N] = actopt( A[M,K] @ W[N,K]^T + bias[N] ) ----------------
// Known-good from R6 profile: fma=58.5%, dur 394us on the 8192x4096x256 layer.
template<int K, int N, bool TANH>
__global__ __launch_bounds__(256)
void sgemm128_kernel(const float* __restrict__ A, const float* __restrict__ W,
                     const float* __restrict__ bias, float* __restrict__ C,
                     int M) {
    constexpr int BM = 128, BN = 128, BK = 16;
    constexpr int NK = K / BK;
    __shared__ float As[2][BK][BM];
    __shared__ float Bs[2][BK][BN];

    const int tid = threadIdx.x;
    const int m0 = blockIdx.y * BM;
    const int n0 = blockIdx.x * BN;

    const int lrow0 = tid >> 2;            // 0..63
    const int lk    = (tid & 3) * 4;       // 0,4,8,12
    const float* Ap = A + (size_t)m0 * K;
    const float* Wp = W + (size_t)n0 * K;

    const int tx = tid & 15;               // N direction
    const int ty = tid >> 4;               // M direction

    float acc[8][8];
    #pragma unroll
    for (int i = 0; i < 8; i++)
        #pragma unroll
        for (int j = 0; j < 8; j++) acc[i][j] = 0.f;

    {
        #pragma unroll
        for (int h = 0; h < 2; h++) {
            int row = lrow0 + h * 64;
            float4 va = *(const float4*)(Ap + (size_t)row * K + lk);
            As[0][lk + 0][row] = va.x; As[0][lk + 1][row] = va.y;
            As[0][lk + 2][row] = va.z; As[0][lk + 3][row] = va.w;
            float4 vb = *(const float4*)(Wp + (size_t)row * K + lk);
            Bs[0][lk + 0][row] = vb.x; Bs[0][lk + 1][row] = vb.y;
            Bs[0][lk + 2][row] = vb.z; Bs[0][lk + 3][row] = vb.w;
        }
    }
    __syncthreads();

    #pragma unroll 1
    for (int kt = 0; kt < NK; kt++) {
        const int s = kt & 1;
        float4 pa[2], pb[2];
        const bool more = (kt + 1 < NK);
        if (more) {
            int k0n = (kt + 1) * BK;
            #pragma unroll
            for (int h = 0; h < 2; h++) {
                int row = lrow0 + h * 64;
                pa[h] = *(const float4*)(Ap + (size_t)row * K + k0n + lk);
                pb[h] = *(const float4*)(Wp + (size_t)row * K + k0n + lk);
            }
        }

        #pragma unroll
        for (int k = 0; k < BK; k++) {
            float4 a0 = *(const float4*)&As[s][k][ty * 4];
            float4 a1 = *(const float4*)&As[s][k][64 + ty * 4];
            float4 b0 = *(const float4*)&Bs[s][k][tx * 4];
            float4 b1 = *(const float4*)&Bs[s][k][64 + tx * 4];
            float av[8] = {a0.x, a0.y, a0.z, a0.w, a1.x, a1.y, a1.z, a1.w};
            float bv[8] = {b0.x, b0.y, b0.z, b0.w, b1.x, b1.y, b1.z, b1.w};
            #pragma unroll
            for (int i = 0; i < 8; i++)
                #pragma unroll
                for (int j = 0; j < 8; j++)
                    acc[i][j] = fmaf(av[i], bv[j], acc[i][j]);
        }

        if (more) {
            const int d = s ^ 1;
            #pragma unroll
            for (int h = 0; h < 2; h++) {
                int row = lrow0 + h * 64;
                As[d][lk + 0][row] = pa[h].x; As[d][lk + 1][row] = pa[h].y;
                As[d][lk + 2][row] = pa[h].z; As[d][lk + 3][row] = pa[h].w;
                Bs[d][lk + 0][row] = pb[h].x; Bs[d][lk + 1][row] = pb[h].y;
                Bs[d][lk + 2][row] = pb[h].z; Bs[d][lk + 3][row] = pb[h].w;
            }
        }
        __syncthreads();
    }

    #pragma unroll
    for (int i = 0; i < 8; i++) {
        int r = m0 + ((i < 4) ? (ty * 4 + i) : (64 + ty * 4 + i - 4));
        #pragma unroll
        for (int g = 0; g < 2; g++) {
            int c0 = n0 + g * 64 + tx * 4;
            float4 v;
            float* vp = &v.x;
            #pragma unroll
            for (int j = 0; j < 4; j++) {
                float val = acc[i][g * 4 + j] + bias[c0 + j];
                if (TANH) val = tanhf(val);
                vp[j] = val;
            }
            *(float4*)(C + (size_t)r * N + c0) = v;
        }
    }
}

// ---------------- warp reductions ----------------
__device__ __forceinline__ float warp_sum(float v) {
    #pragma unroll
    for (int o = 16; o; o >>= 1) v += __shfl_xor_sync(0xffffffffu, v, o);
    return v;
}
__device__ __forceinline__ float warp_max(float v) {
    #pragma unroll
    for (int o = 16; o; o >>= 1) v = fmaxf(v, __shfl_xor_sync(0xffffffffu, v, o));
    return v;
}

// ---------------- warp-per-row fused head + KL-solver ----------------
// One 32-thread CTA per batch row. Row data (rm1, bb) lives in 32KB static
// smem (7 CTAs/SM within the 228KB carveout); every reduction is shfl-only
// -> ZERO barriers in the 20-iter loop. Lane l owns element groups
// g = l + 32e (e=0..31), elems 4g..4g+3 -> coalesced float4 gmem access,
// smem reads phase out at conflict degree <=2.
__global__ __launch_bounds__(32)
void solver_kernel(const float* __restrict__ T1, const float* __restrict__ W2,
                   const float* __restrict__ b2, const float* __restrict__ H2,
                   const float* __restrict__ logb, const float* __restrict__ klb,
                   const int* __restrict__ actions_left, float* __restrict__ out) {
    // __align__(16): read via LDS.128; float2 alone only guarantees 8B.
    __shared__ __align__(16) float2 sd[OUT_DIM];   // 32 KB: (rm1, bb)
    const int row = blockIdx.x;
    const int l   = threadIdx.x;
    const size_t base = (size_t)row * OUT_DIM;

    // --- kl head: dot(T1[row], W2[0]) + b2[0] ---
    float p = 0.f;
    #pragma unroll
    for (int e = 0; e < 8; e++) {
        int k = l + 32 * e;
        p += T1[(size_t)row * HID + k] * W2[k];
    }
    p = warp_sum(p);
    float z  = (p + b2[0]) - __logf((float)(*actions_left));
    float kt = (1.f / (1.f + __expf(-z))) * klb[row] + 1e-6f;

    // --- pass 1: gmem -> smem (h2, lb), track max(h2+lb) ---
    const float4* H4 = (const float4*)(H2 + base);
    const float4* B4 = (const float4*)(logb + base);
    float mx = -INFINITY;
    #pragma unroll 8
    for (int e = 0; e < 32; e++) {
        int g = l + 32 * e;
        float4 h = H4[g], b = B4[g];
        sd[4*g + 0] = make_float2(h.x, b.x);
        sd[4*g + 1] = make_float2(h.y, b.y);
        sd[4*g + 2] = make_float2(h.z, b.z);
        sd[4*g + 3] = make_float2(h.w, b.w);
        mx = fmaxf(mx, fmaxf(fmaxf(h.x + b.x, h.y + b.y),
                             fmaxf(h.z + b.z, h.w + b.w)));
    }
    mx = warp_max(mx);

    // --- pass 2: logsumexp(h2 + lb) ---
    float se = 0.f;
    #pragma unroll 8
    for (int e = 0; e < 32; e++) {
        int g = l + 32 * e;
        float4 q0 = *(const float4*)&sd[4*g + 0];   // (h0,lb0,h1,lb1)
        float4 q1 = *(const float4*)&sd[4*g + 2];
        se += __expf(q0.x + q0.y - mx) + __expf(q0.z + q0.w - mx)
            + __expf(q1.x + q1.y - mx) + __expf(q1.z + q1.w - mx);
    }
    se = warp_sum(se);
    const float S = mx + __logf(se);                // logsumexp

    // --- pass 3: (h2, lb) -> (rm1, bb); usum = sum(bb*rm1) = sum(a - b) ---
    float usum = 0.f;
    #pragma unroll 8
    for (int e = 0; e < 32; e++) {
        int g = l + 32 * e;
        #pragma unroll
        for (int c = 0; c < 4; c++) {
            float2 v = sd[4*g + c];
            float rm1 = __expf(v.x - S) - 1.f;      // a/b - 1
            float bb  = __expf(v.y);                // b
            sd[4*g + c] = make_float2(rm1, bb);
            usum = fmaf(bb, rm1, usum);
        }
    }
    usum = warp_sum(usum);

    // --- 20 Newton/bisection steps (shfl-only reductions, no barriers) ---
    // t = x/b = 1 + alpha*rm1, clamped away from 0 so log stays finite even
    // if a underflowed (its true contribution is ~0).
    // d = sum(u*(L+1)) = sum(u*L) + usum, with u = bb*rm1 (usum hoisted).
    float alpha = 1.f, bot = 0.f, top = 1.f;
    #pragma unroll 1
    for (int it = 0; it < 20; it++) {
        float klp = 0.f, dq = 0.f;
        #pragma unroll 8
        for (int e = 0; e < 32; e++) {
            int g = l + 32 * e;
            float4 q0 = *(const float4*)&sd[4*g + 0];   // (rm1,bb,rm1,bb)
            float4 q1 = *(const float4*)&sd[4*g + 2];
            float rm[4] = {q0.x, q0.z, q1.x, q1.z};
            float bv[4] = {q0.y, q0.w, q1.y, q1.w};
            #pragma unroll
            for (int c = 0; c < 4; c++) {
                float t = fmaxf(fmaf(alpha, rm[c], 1.f), 1e-30f);
                float L = __logf(t);                    // logx - logb
                klp = fmaf(bv[c] * t, L, klp);          // sum x*(logx-logb)
                dq  = fmaf(bv[c] * rm[c], L, dq);       // sum u*L
            }
        }
        klp = warp_sum(klp);
        dq  = warp_sum(dq);
        float kl = klp;
        float d  = dq + usum;
        bot = (kt >= kl) ? alpha : bot;                 // matches jnp.where
        top = (kt <= kl) ? alpha : top;
        float delta = (kt - kl) / (d + 1e-12f);
        float lo = bot * 0.9375f + top * 0.0625f;
        float hi = 0.5f * (bot + top);
        alpha = fminf(fmaxf(alpha + delta, lo), hi);
    }

    // --- final eval at converged alpha; softmax(logx) = x / sum(x) ---
    float klp = 0.f, sp = 0.f;
    #pragma unroll 8
    for (int e = 0; e < 32; e++) {
        int g = l + 32 * e;
        #pragma unroll
        for (int c = 0; c < 4; c++) {
            float2 v = sd[4*g + c];
            float t  = fmaxf(fmaf(alpha, v.x, 1.f), 1e-30f);
            float L  = __logf(t);
            float xv = v.y * t;
            klp = fmaf(xv, L, klp);
            sp += xv;
            sd[4*g + c].x = xv;                     // stash for output pass
        }
    }
    klp = warp_sum(klp);
    sp  = warp_sum(sp);
    float inv = 1.f / sp;

    float4* O4 = (float4*)(out + base);
    #pragma unroll 8
    for (int e = 0; e < 32; e++) {
        int g = l + 32 * e;
        float4 o;
        o.x = sd[4*g + 0].x * inv;
        o.y = sd[4*g + 1].x * inv;
        o.z = sd[4*g + 2].x * inv;
        o.w = sd[4*g + 3].x * inv;
        O4[g] = o;
    }
    if (l == 0) {
        float dk = klp - kt;
        out[(size_t)BATCH * OUT_DIM + row] = dk * dk;
    }
}

// ---------------- launch ----------------
extern "C" void kernel_launch(void* const* d_in, const int* in_sizes, int n_in,
                              void* d_out, int out_size) {
    const float* x    = (const float*)d_in[0];
    const float* klb  = (const float*)d_in[1];
    const float* logb = (const float*)d_in[2];
    const float* W0   = (const float*)d_in[3];
    const float* b0   = (const float*)d_in[4];
    const float* W1   = (const float*)d_in[5];
    const float* b1   = (const float*)d_in[6];
    const float* W2   = (const float*)d_in[7];
    const float* b2   = (const float*)d_in[8];
    const int*   al   = (const int*)  d_in[9];
    float* out = (float*)d_out;

    float *Xc, *W0p, *T0, *T1, *H2;
    cudaGetSymbolAddress((void**)&Xc,  g_Xc);
    cudaGetSymbolAddress((void**)&W0p, g_W0p);
    cudaGetSymbolAddress((void**)&T0,  g_T0);
    cudaGetSymbolAddress((void**)&T1,  g_T1);
    cudaGetSymbolAddress((void**)&H2,  g_H2);

    // prep (single launch covers both Xc and W0p ranges)
    prep_kernel<<<(BATCH * K0PAD + 255) / 256, 256>>>(x, klb, W0, Xc, W0p);

    // layer 0: T0 = tanh(Xc @ W0p^T + b0)   [8192,256], K=80
    {
        dim3 grid(HID / 128, BATCH / 128);
        sgemm128_kernel<K0PAD, HID, true><<<grid, 256>>>(Xc, W0p, b0, T0, BATCH);
    }
    // layer 1: T1 = tanh(T0 @ W1^T + b1)    [8192,256], K=256
    {
        dim3 grid(HID / 128, BATCH / 128);
        sgemm128_kernel<HID, HID, true><<<grid, 256>>>(T0, W1, b1, T1, BATCH);
    }
    // layer 2 (main cols 1..4096): H2 = T1 @ W2[1:]^T + b2[1:]   [8192,4096], K=256
    {
        dim3 grid(OUT_DIM / 128, BATCH / 128);
        sgemm128_kernel<HID, OUT_DIM, false><<<grid, 256>>>(T1, W2 + HID, b2 + 1, H2, BATCH);
    }
    // warp-per-row fused head + solver + output
    solver_kernel<<<BATCH, 32>>>(T1, W2, b2, H2, logb, klb, al, out);
}

// round 13
// speedup vs baseline: 1.2484x; 1.2039x over previous
#include <cuda_runtime.h>
#include <cuda_bf16.h>
#include <math.h>
#include <stdint.h>

// Problem constants
#define BATCH   8192
#define IN_DIM  64
#define HID     256
#define OUT_DIM 4096          // main distribution columns (h2 cols 1..4096)
#define K0PAD   80            // IN_DIM+1 padded to multiple of 16
#define LN2F    0.69314718055994531f

// ---------------- static device scratch (no dynamic allocation allowed) ----------------
__device__ __align__(256) float g_Xc [BATCH * K0PAD];
__device__ __align__(256) float g_W0p[HID * K0PAD];
__device__ __align__(256) float g_T0 [BATCH * HID];
__device__ __align__(256) float g_T1 [BATCH * HID];
__device__ __align__(256) float g_H2 [(size_t)BATCH * OUT_DIM];

// ---------------- prep: concat+pad X, pad W0, in one launch ----------------
__global__ void prep_kernel(const float* __restrict__ x,
                            const float* __restrict__ klb,
                            const float* __restrict__ W0,
                            float* __restrict__ Xc,
                            float* __restrict__ W0p) {
    int i = blockIdx.x * blockDim.x + threadIdx.x;
    if (i < BATCH * K0PAD) {
        int r = i / K0PAD, c = i % K0PAD;
        float v = 0.f;
        if (c < IN_DIM)       v = x[r * IN_DIM + c];
        else if (c == IN_DIM) v = klb[r];
        Xc[i] = v;
    }
    if (i < HID * K0PAD) {
        int r = i / K0PAD, c = i % K0PAD;
        W0p[i] = (c < IN_DIM + 1) ? W0[r * (IN_DIM + 1) + c] : 0.f;
    }
}

// ---------------- SGEMM (unchanged; profiled fma=58.5%) ----------------
template<int K, int N, bool TANH>
__global__ __launch_bounds__(256)
void sgemm128_kernel(const float* __restrict__ A, const float* __restrict__ W,
                     const float* __restrict__ bias, float* __restrict__ C,
                     int M) {
    constexpr int BM = 128, BN = 128, BK = 16;
    constexpr int NK = K / BK;
    __shared__ float As[2][BK][BM];
    __shared__ float Bs[2][BK][BN];

    const int tid = threadIdx.x;
    const int m0 = blockIdx.y * BM;
    const int n0 = blockIdx.x * BN;

    const int lrow0 = tid >> 2;
    const int lk    = (tid & 3) * 4;
    const float* Ap = A + (size_t)m0 * K;
    const float* Wp = W + (size_t)n0 * K;

    const int tx = tid & 15;
    const int ty = tid >> 4;

    float acc[8][8];
    #pragma unroll
    for (int i = 0; i < 8; i++)
        #pragma unroll
        for (int j = 0; j < 8; j++) acc[i][j] = 0.f;

    {
        #pragma unroll
        for (int h = 0; h < 2; h++) {
            int row = lrow0 + h * 64;
            float4 va = *(const float4*)(Ap + (size_t)row * K + lk);
            As[0][lk + 0][row] = va.x; As[0][lk + 1][row] = va.y;
            As[0][lk + 2][row] = va.z; As[0][lk + 3][row] = va.w;
            float4 vb = *(const float4*)(Wp + (size_t)row * K + lk);
            Bs[0][lk + 0][row] = vb.x; Bs[0][lk + 1][row] = vb.y;
            Bs[0][lk + 2][row] = vb.z; Bs[0][lk + 3][row] = vb.w;
        }
    }
    __syncthreads();

    #pragma unroll 1
    for (int kt = 0; kt < NK; kt++) {
        const int s = kt & 1;
        float4 pa[2], pb[2];
        const bool more = (kt + 1 < NK);
        if (more) {
            int k0n = (kt + 1) * BK;
            #pragma unroll
            for (int h = 0; h < 2; h++) {
                int row = lrow0 + h * 64;
                pa[h] = *(const float4*)(Ap + (size_t)row * K + k0n + lk);
                pb[h] = *(const float4*)(Wp + (size_t)row * K + k0n + lk);
            }
        }

        #pragma unroll
        for (int k = 0; k < BK; k++) {
            float4 a0 = *(const float4*)&As[s][k][ty * 4];
            float4 a1 = *(const float4*)&As[s][k][64 + ty * 4];
            float4 b0 = *(const float4*)&Bs[s][k][tx * 4];
            float4 b1 = *(const float4*)&Bs[s][k][64 + tx * 4];
            float av[8] = {a0.x, a0.y, a0.z, a0.w, a1.x, a1.y, a1.z, a1.w};
            float bv[8] = {b0.x, b0.y, b0.z, b0.w, b1.x, b1.y, b1.z, b1.w};
            #pragma unroll
            for (int i = 0; i < 8; i++)
                #pragma unroll
                for (int j = 0; j < 8; j++)
                    acc[i][j] = fmaf(av[i], bv[j], acc[i][j]);
        }

        if (more) {
            const int d = s ^ 1;
            #pragma unroll
            for (int h = 0; h < 2; h++) {
                int row = lrow0 + h * 64;
                As[d][lk + 0][row] = pa[h].x; As[d][lk + 1][row] = pa[h].y;
                As[d][lk + 2][row] = pa[h].z; As[d][lk + 3][row] = pa[h].w;
                Bs[d][lk + 0][row] = pb[h].x; Bs[d][lk + 1][row] = pb[h].y;
                Bs[d][lk + 2][row] = pb[h].z; Bs[d][lk + 3][row] = pb[h].w;
            }
        }
        __syncthreads();
    }

    #pragma unroll
    for (int i = 0; i < 8; i++) {
        int r = m0 + ((i < 4) ? (ty * 4 + i) : (64 + ty * 4 + i - 4));
        #pragma unroll
        for (int g = 0; g < 2; g++) {
            int c0 = n0 + g * 64 + tx * 4;
            float4 v;
            float* vp = &v.x;
            #pragma unroll
            for (int j = 0; j < 4; j++) {
                float val = acc[i][g * 4 + j] + bias[c0 + j];
                if (TANH) val = tanhf(val);
                vp[j] = val;
            }
            *(float4*)(C + (size_t)r * N + c0) = v;
        }
    }
}

// ---------------- reductions (256 threads, 8 warps) ----------------
__device__ __forceinline__ float warp_sum(float v) {
    #pragma unroll
    for (int o = 16; o; o >>= 1) v += __shfl_xor_sync(0xffffffffu, v, o);
    return v;
}
__device__ __forceinline__ float warp_max(float v) {
    #pragma unroll
    for (int o = 16; o; o >>= 1) v = fmaxf(v, __shfl_xor_sync(0xffffffffu, v, o));
    return v;
}
// sm must hold >= 18 floats
__device__ __forceinline__ float blk_sum(float v, float* sm) {
    int w = threadIdx.x >> 5, l = threadIdx.x & 31;
    v = warp_sum(v);
    if (l == 0) sm[w] = v;
    __syncthreads();
    if (w == 0) {
        float t = (l < 8) ? sm[l] : 0.f;
        t = warp_sum(t);
        if (l == 0) sm[16] = t;
    }
    __syncthreads();
    return sm[16];
}
__device__ __forceinline__ float blk_max(float v, float* sm) {
    int w = threadIdx.x >> 5, l = threadIdx.x & 31;
    v = warp_max(v);
    if (l == 0) sm[w] = v;
    __syncthreads();
    if (w == 0) {
        float t = (l < 8) ? sm[l] : -INFINITY;
        t = warp_max(t);
        if (l == 0) sm[16] = t;
    }
    __syncthreads();
    return sm[16];
}
__device__ __forceinline__ float2 blk_sum2(float a, float b, float* sm) {
    int w = threadIdx.x >> 5, l = threadIdx.x & 31;
    a = warp_sum(a); b = warp_sum(b);
    if (l == 0) { sm[w] = a; sm[8 + w] = b; }
    __syncthreads();
    if (w == 0) {
        float ta = (l < 8) ? sm[l] : 0.f;
        float tb = (l < 8) ? sm[8 + l] : 0.f;
        ta = warp_sum(ta); tb = warp_sum(tb);
        if (l == 0) { sm[16] = ta; sm[17] = tb; }
    }
    __syncthreads();
    return make_float2(sm[16], sm[17]);
}

// ---------------- fused head + KL-solver, 256 thr/row, register-resident ----------------
// 16 elems/thread live in registers (rm1, b, u=b*rm1). Inner loop per element:
// 1 FMA (t) + 1 FMNMX (clamp) + 1 MUFU (lg2) + 2 FMA (P2,Q2). No LDS in loop.
// kl = ln2*(P2 + alpha*Q2); d = ln2*Q2 + usum  (ln2 folded out of the loop).
__global__ __launch_bounds__(256)
void solver_kernel(const float* __restrict__ T1, const float* __restrict__ W2,
                   const float* __restrict__ b2, const float* __restrict__ H2,
                   const float* __restrict__ logb, const float* __restrict__ klb,
                   const int* __restrict__ actions_left, float* __restrict__ out) {
    __shared__ float sm[24];
    const int row = blockIdx.x;
    const int tid = threadIdx.x;
    const size_t base = (size_t)row * OUT_DIM;

    // --- kl head: dot(T1[row], W2[0]) + b2[0]  (one element per thread) ---
    float p = T1[(size_t)row * HID + tid] * W2[tid];
    p = blk_sum(p, sm);
    float z  = (p + b2[0]) - __logf((float)(*actions_left));
    float kt = (1.f / (1.f + __expf(-z))) * klb[row] + 1e-6f;

    // --- load 16 elems/thread: chunk c = tid + 256*e holds elems 4c..4c+3 ---
    const float4* H4 = (const float4*)(H2 + base);
    const float4* B4 = (const float4*)(logb + base);
    float h2v[16], lb[16];
    float mx = -INFINITY;
    #pragma unroll
    for (int e = 0; e < 4; e++) {
        int c = tid + 256 * e;
        float4 h = H4[c], b = B4[c];
        h2v[e*4+0] = h.x; h2v[e*4+1] = h.y; h2v[e*4+2] = h.z; h2v[e*4+3] = h.w;
        lb [e*4+0] = b.x; lb [e*4+1] = b.y; lb [e*4+2] = b.z; lb [e*4+3] = b.w;
        mx = fmaxf(mx, fmaxf(fmaxf(h.x + b.x, h.y + b.y),
                             fmaxf(h.z + b.z, h.w + b.w)));
    }
    mx = blk_max(mx, sm);
    float se = 0.f;
    #pragma unroll
    for (int j = 0; j < 16; j++) se += __expf(h2v[j] + lb[j] - mx);
    se = blk_sum(se, sm);
    const float S = mx + __logf(se);                 // logsumexp(h2+lb)

    // --- transform to (rm1, bb, uu); usum = sum(u) = sum(a-b) ---
    float rm1[16], bb[16], uu[16];
    float usum = 0.f;
    #pragma unroll
    for (int j = 0; j < 16; j++) {
        float r = __expf(h2v[j] - S);                // a/b
        float b = __expf(lb[j]);                     // b
        rm1[j] = r - 1.f;
        bb[j]  = b;
        uu[j]  = b * (r - 1.f);                      // a - b
        usum  += uu[j];
    }
    usum = blk_sum(usum, sm);

    // --- 20 Newton/bisection steps ---
    // t = 1 + alpha*rm1 clamped away from 0 (underflowed a contributes ~0).
    float alpha = 1.f, bot = 0.f, top = 1.f;
    #pragma unroll 1
    for (int it = 0; it < 20; it++) {
        float P2 = 0.f, Q2 = 0.f;
        #pragma unroll
        for (int j = 0; j < 16; j++) {
            float t  = fmaxf(fmaf(alpha, rm1[j], 1.f), 1e-30f);
            float lg = __log2f(t);                   // raw MUFU lg2
            P2 = fmaf(bb[j], lg, P2);                // sum b*lg2(t)
            Q2 = fmaf(uu[j], lg, Q2);                // sum u*lg2(t)
        }
        float2 pq = blk_sum2(P2, Q2, sm);
        float kl = LN2F * fmaf(alpha, pq.y, pq.x);   // ln2*(P2 + a*Q2)
        float d  = fmaf(LN2F, pq.y, usum);           // ln2*Q2 + usum
        bot = (kt >= kl) ? alpha : bot;              // matches jnp.where
        top = (kt <= kl) ? alpha : top;
        float delta = (kt - kl) / (d + 1e-12f);
        float lo = bot * 0.9375f + top * 0.0625f;
        float hi = 0.5f * (bot + top);
        alpha = fminf(fmaxf(alpha + delta, lo), hi);
    }

    // --- final eval; softmax(logx) = x / sum(x) ---
    float klp = 0.f, sp = 0.f;
    #pragma unroll
    for (int j = 0; j < 16; j++) {
        float t  = fmaxf(fmaf(alpha, rm1[j], 1.f), 1e-30f);
        float lg = __log2f(t);
        float xv = bb[j] * t;
        klp = fmaf(xv, lg, klp);
        sp += xv;
        uu[j] = xv;                                  // stash x values
    }
    float2 ks = blk_sum2(klp, sp, sm);
    float kl_f = LN2F * ks.x;
    float inv  = 1.f / ks.y;

    float4* O4 = (float4*)(out + base);
    #pragma unroll
    for (int e = 0; e < 4; e++) {
        int c = tid + 256 * e;
        float4 o;
        o.x = uu[e*4+0] * inv; o.y = uu[e*4+1] * inv;
        o.z = uu[e*4+2] * inv; o.w = uu[e*4+3] * inv;
        O4[c] = o;
    }
    if (tid == 0) {
        float dk = kl_f - kt;
        out[(size_t)BATCH * OUT_DIM + row] = dk * dk;
    }
}

// ---------------- launch ----------------
extern "C" void kernel_launch(void* const* d_in, const int* in_sizes, int n_in,
                              void* d_out, int out_size) {
    const float* x    = (const float*)d_in[0];
    const float* klb  = (const float*)d_in[1];
    const float* logb = (const float*)d_in[2];
    const float* W0   = (const float*)d_in[3];
    const float* b0   = (const float*)d_in[4];
    const float* W1   = (const float*)d_in[5];
    const float* b1   = (const float*)d_in[6];
    const float* W2   = (const float*)d_in[7];
    const float* b2   = (const float*)d_in[8];
    const int*   al   = (const int*)  d_in[9];
    float* out = (float*)d_out;

    float *Xc, *W0p, *T0, *T1, *H2;
    cudaGetSymbolAddress((void**)&Xc,  g_Xc);
    cudaGetSymbolAddress((void**)&W0p, g_W0p);
    cudaGetSymbolAddress((void**)&T0,  g_T0);
    cudaGetSymbolAddress((void**)&T1,  g_T1);
    cudaGetSymbolAddress((void**)&H2,  g_H2);

    // prep (single launch covers both Xc and W0p ranges)
    prep_kernel<<<(BATCH * K0PAD + 255) / 256, 256>>>(x, klb, W0, Xc, W0p);

    // layer 0: T0 = tanh(Xc @ W0p^T + b0)   [8192,256], K=80
    {
        dim3 grid(HID / 128, BATCH / 128);
        sgemm128_kernel<K0PAD, HID, true><<<grid, 256>>>(Xc, W0p, b0, T0, BATCH);
    }
    // layer 1: T1 = tanh(T0 @ W1^T + b1)    [8192,256], K=256
    {
        dim3 grid(HID / 128, BATCH / 128);
        sgemm128_kernel<HID, HID, true><<<grid, 256>>>(T0, W1, b1, T1, BATCH);
    }
    // layer 2 (main cols 1..4096): H2 = T1 @ W2[1:]^T + b2[1:]   [8192,4096], K=256
    {
        dim3 grid(OUT_DIM / 128, BATCH / 128);
        sgemm128_kernel<HID, OUT_DIM, false><<<grid, 256>>>(T1, W2 + HID, b2 + 1, H2, BATCH);
    }
    // register-resident fused head + solver + output (256 thr/row)
    solver_kernel<<<BATCH, 256>>>(T1, W2, b2, H2, logb, klb, al, out);
}